// round 9
// baseline (speedup 1.0000x reference)
#include <cuda_runtime.h>
#include <math.h>

#define NN 100000
#define EE 1600000
#define HC 64
#define IN_DIM 128

#define XS_WORDS (128 * 68)
#define WS_WORDS (64 * 72)
#define GEMM_SMEM_BYTES ((XS_WORDS + WS_WORDS) * 4)

// ---------------- scratch (device globals, allocation-free) ----------------
// g_xp holds xp in interleaved-pair layout: element 2c   = xp[node][c]
//                                           element 2c+1 = xp[node][c+32]  (c = 0..31)
static __device__ float  g_xp[(size_t)NN * HC];
static __device__ float4 g_as4[NN];               // a_src [N,4]
static __device__ float4 g_ad4[NN];               // a_dst [N,4]
static __device__ float4 g_rcp4[NN];              // per-node 1/(sum exp(l))
static __device__ int    g_cnt[NN];               // degree histogram
static __device__ int2   g_fc[NN];                // {row start, fill cursor}
static __device__ int    g_rowptr[NN + 1];        // CSR row pointers
static __device__ int    g_bsum[512];             // scan partials
static __device__ int    g_boff[512];             // scan offsets
static __device__ int    g_csr_src[EE];           // CSR src ids

__device__ __forceinline__ float lrelu(float v) { return v >= 0.f ? v : 0.2f * v; }

__device__ __forceinline__ float f2tf(float f) {
    unsigned u;
    asm("cvt.rna.tf32.f32 %0, %1;" : "=r"(u) : "f"(f));
    return __uint_as_float(u);
}
__device__ __forceinline__ void mma_tf32(float4& d,
    float a0, float a1, float a2, float a3, float b0, float b1)
{
    asm("mma.sync.aligned.m16n8k8.row.col.f32.tf32.tf32.f32 "
        "{%0,%1,%2,%3}, {%4,%5,%6,%7}, {%8,%9}, {%0,%1,%2,%3};"
        : "+f"(d.x), "+f"(d.y), "+f"(d.z), "+f"(d.w)
        : "r"(__float_as_uint(a0)), "r"(__float_as_uint(a1)),
          "r"(__float_as_uint(a2)), "r"(__float_as_uint(a3)),
          "r"(__float_as_uint(b0)), "r"(__float_as_uint(b1)));
}

// ---------------- init: zero histogram ----------------
__global__ void init_kernel(int n) {
    int i = blockIdx.x * blockDim.x + threadIdx.x;
    if (i < n) g_cnt[i] = 0;
}

// ---------------- GEMM: xp = x @ W via tf32 tensor cores + attn epilogue ----------------
// 128x64 block tile, 8 warps at 32(m)x32(n): 8 MMAs per 16 LDS per k8 (2 LDS/MMA).
// Same conflict-free stride-68/72 staging layouts as R7/R8. Dynamic smem (53 KB).
__global__ __launch_bounds__(256) void gemm_kernel(
    const float* __restrict__ x, const float* __restrict__ W,
    const float* __restrict__ att_src, const float* __restrict__ att_dst, int n)
{
    extern __shared__ float smem[];
    float* xs = smem;              // [row 0..127][k-half 0..63], stride 68 (reused for C)
    float* ws = smem + XS_WORDS;   // [k-half][col], stride 72
    int tid = threadIdx.x;
    int lane = tid & 31, warp = tid >> 5;
    int wm = warp & 3, wn = warp >> 2;
    int gid = lane >> 2, tig = lane & 3;
    int r0 = blockIdx.x * 128;

    float4 c[2][4];
#pragma unroll
    for (int f = 0; f < 2; f++)
#pragma unroll
        for (int t = 0; t < 4; t++) c[f][t] = make_float4(0.f, 0.f, 0.f, 0.f);

    for (int kh = 0; kh < 2; kh++) {
        // stage x tile: 128 rows x 64 k, tf32-converted
#pragma unroll
        for (int q = 0; q < 8; q++) {
            int idx = tid + q * 256;           // 0..2047
            int row = idx >> 4, k4 = idx & 15;
            float4 v = make_float4(0.f, 0.f, 0.f, 0.f);
            int grow = r0 + row;
            if (grow < n)
                v = *(const float4*)(x + (size_t)grow * IN_DIM + kh * 64 + k4 * 4);
            *(float4*)(xs + row * 68 + k4 * 4) =
                make_float4(f2tf(v.x), f2tf(v.y), f2tf(v.z), f2tf(v.w));
        }
        // stage W half: ws[k][col], tf32-converted
#pragma unroll
        for (int q = 0; q < 4; q++) {
            int idx = tid + q * 256;
            int k = idx >> 4, c4 = idx & 15;
            float4 v = *(const float4*)(W + (size_t)(kh * 64 + k) * HC + c4 * 4);
            *(float4*)(ws + k * 72 + c4 * 4) =
                make_float4(f2tf(v.x), f2tf(v.y), f2tf(v.z), f2tf(v.w));
        }
        __syncthreads();
#pragma unroll
        for (int k8 = 0; k8 < 8; k8++) {
            int kb = k8 * 8;
            const float* xr0 = xs + (32 * wm + gid) * 68 + kb + tig;
            float a0 = xr0[0];
            float a1 = xr0[8 * 68];
            float a2 = xr0[4];
            float a3 = xr0[8 * 68 + 4];
            const float* xr1 = xr0 + 16 * 68;
            float a4 = xr1[0];
            float a5 = xr1[8 * 68];
            float a6 = xr1[4];
            float a7 = xr1[8 * 68 + 4];
            const float* wr = ws + (kb + tig) * 72 + 32 * wn + gid;
#pragma unroll
            for (int t = 0; t < 4; t++) {
                float b0 = wr[8 * t];
                float b1 = wr[4 * 72 + 8 * t];
                mma_tf32(c[0][t], a0, a1, a2, a3, b0, b1);
                mma_tf32(c[1][t], a4, a5, a6, a7, b0, b1);
            }
        }
        __syncthreads();
    }

    // write C frags into xs [row 0..127][col 0..63], stride 68
    {
        int cb = 32 * wn + 2 * tig;
#pragma unroll
        for (int f = 0; f < 2; f++) {
            int rlo = 32 * wm + 16 * f + gid;
#pragma unroll
            for (int t = 0; t < 4; t++) {
                *(float2*)(xs + rlo * 68 + cb + 8 * t)       = make_float2(c[f][t].x, c[f][t].y);
                *(float2*)(xs + (rlo + 8) * 68 + cb + 8 * t) = make_float2(c[f][t].z, c[f][t].w);
            }
        }
    }
    __syncthreads();

    // epilogue: thread = (row, half hh). hh covers cols 32hh..32hh+31 = heads 2hh, 2hh+1.
    {
        int row = tid >> 1, hh = tid & 1;
        int grow = r0 + row;
        if (grow < n) {
            float as0 = 0.f, as1 = 0.f, ad0 = 0.f, ad1 = 0.f;
#pragma unroll
            for (int i = 0; i < 4; i++) {
                float4 v  = *(const float4*)(xs + row * 68 + 32 * hh + 4 * i);
                float4 s4 = __ldg((const float4*)(att_src + 32 * hh + 4 * i));
                float4 d4 = __ldg((const float4*)(att_dst + 32 * hh + 4 * i));
                as0 += v.x * s4.x + v.y * s4.y + v.z * s4.z + v.w * s4.w;
                ad0 += v.x * d4.x + v.y * d4.y + v.z * d4.z + v.w * d4.w;
            }
#pragma unroll
            for (int i = 4; i < 8; i++) {
                float4 v  = *(const float4*)(xs + row * 68 + 32 * hh + 4 * i);
                float4 s4 = __ldg((const float4*)(att_src + 32 * hh + 4 * i));
                float4 d4 = __ldg((const float4*)(att_dst + 32 * hh + 4 * i));
                as1 += v.x * s4.x + v.y * s4.y + v.z * s4.z + v.w * s4.w;
                ad1 += v.x * d4.x + v.y * d4.y + v.z * d4.z + v.w * d4.w;
            }
            ((float*)&g_as4[grow])[2 * hh]     = as0;
            ((float*)&g_as4[grow])[2 * hh + 1] = as1;
            ((float*)&g_ad4[grow])[2 * hh]     = ad0;
            ((float*)&g_ad4[grow])[2 * hh + 1] = ad1;
            // xp interleaved pairs: c in [16hh, 16hh+16): (xp[c], xp[c+32])
#pragma unroll
            for (int i = 0; i < 4; i++) {
                float4 A4 = *(const float4*)(xs + row * 68 + 16 * hh + 4 * i);
                float4 B4 = *(const float4*)(xs + row * 68 + 16 * hh + 32 + 4 * i);
                float* dst = g_xp + (size_t)grow * HC + 2 * (16 * hh + 4 * i);
                *(float4*)(dst)     = make_float4(A4.x, B4.x, A4.y, B4.y);
                *(float4*)(dst + 4) = make_float4(A4.z, B4.z, A4.w, B4.w);
            }
        }
    }
}

// ---------------- CSR histogram + fused edge_index float copy ----------------
__global__ void hist_kernel(const int* __restrict__ ei, int e, float* __restrict__ ei_out) {
    int t = blockIdx.x * blockDim.x + threadIdx.x;
    int base = t * 4;
    if (base + 3 < e) {
        int4 d4 = *(const int4*)(ei + e + base);
        atomicAdd(&g_cnt[d4.x], 1);
        atomicAdd(&g_cnt[d4.y], 1);
        atomicAdd(&g_cnt[d4.z], 1);
        atomicAdd(&g_cnt[d4.w], 1);
        if (ei_out) {
            int4 s4 = *(const int4*)(ei + base);
            *(float4*)(ei_out + base) =
                make_float4((float)s4.x, (float)s4.y, (float)s4.z, (float)s4.w);
            *(float4*)(ei_out + e + base) =
                make_float4((float)d4.x, (float)d4.y, (float)d4.z, (float)d4.w);
        }
    } else {
        for (int i = base; i < e; i++) {
            int s = ei[i], d = ei[e + i];
            atomicAdd(&g_cnt[d], 1);
            if (ei_out) { ei_out[i] = (float)s; ei_out[e + i] = (float)d; }
        }
    }
}

__global__ void scan1_kernel(int n) {
    __shared__ int sd[512];
    int t = threadIdx.x, i = blockIdx.x * 512 + t;
    int v = (i < n) ? g_cnt[i] : 0;
    sd[t] = v; __syncthreads();
    for (int off = 1; off < 512; off <<= 1) {
        int x = (t >= off) ? sd[t - off] : 0;
        __syncthreads();
        sd[t] += x;
        __syncthreads();
    }
    if (i < n) g_rowptr[i + 1] = sd[t];
    if (t == 511) g_bsum[blockIdx.x] = sd[511];
}

__global__ void scan2_kernel(int nb) {
    __shared__ int sd[512];
    int t = threadIdx.x;
    int v = (t < nb) ? g_bsum[t] : 0;
    sd[t] = v; __syncthreads();
    for (int off = 1; off < 512; off <<= 1) {
        int x = (t >= off) ? sd[t - off] : 0;
        __syncthreads();
        sd[t] += x;
        __syncthreads();
    }
    g_boff[t] = sd[t] - v;   // exclusive
}

// adds block offsets AND initializes fill cursors {start, 0}
__global__ void scan3_kernel(int n) {
    int t = threadIdx.x;
    int i = blockIdx.x * 512 + t;
    int inc = g_boff[blockIdx.x];
    int prev = 0;
    if (i < n && t > 0) prev = g_rowptr[i];     // scan1 value at i (pre-offset)
    __syncthreads();
    if (i < n) {
        g_rowptr[i + 1] += inc;
        g_fc[i] = make_int2(prev + inc, 0);
        if (i == 0) g_rowptr[0] = 0;
    }
}

__global__ void fill_kernel(const int* __restrict__ ei, int e) {
    int t = blockIdx.x * blockDim.x + threadIdx.x;
    if (t >= e) return;
    int s = ei[t], d = ei[e + t];
    int2* fc = &g_fc[d];
    int pos = atomicAdd(&fc->y, 1);
    g_csr_src[fc->x + pos] = s;
}

// ---------------- fused softmax + aggregation: one warp per dst node ----------------
__global__ __launch_bounds__(256) void aggregate_kernel(
    const float* __restrict__ bias, float* __restrict__ out, int n)
{
    __shared__ float sE[8][32][4];
    int w = (blockIdx.x * 256 + threadIdx.x) >> 5;
    int lane = threadIdx.x & 31, wl = threadIdx.x >> 5;
    if (w >= n) return;                 // uniform per warp

    int start = g_rowptr[w];
    int deg   = g_rowptr[w + 1] - start;
    float4 ad = g_ad4[w];

    float4 ds = make_float4(0.f, 0.f, 0.f, 0.f);
    float acc0 = 0.f, acc1 = 0.f;
    int h0 = lane >> 4;      // head of col=lane; col=lane+32 is head h0+2

    for (int base = 0; base < deg; base += 32) {
        int i = base + lane;
        int s = 0;
        float4 ev = make_float4(0.f, 0.f, 0.f, 0.f);
        if (i < deg) {
            s = g_csr_src[start + i];
            float4 a = g_as4[s];
            ev.x = __expf(lrelu(a.x + ad.x));
            ev.y = __expf(lrelu(a.y + ad.y));
            ev.z = __expf(lrelu(a.z + ad.z));
            ev.w = __expf(lrelu(a.w + ad.w));
            ds.x += ev.x; ds.y += ev.y; ds.z += ev.z; ds.w += ev.w;
        }
        sE[wl][lane][0] = ev.x; sE[wl][lane][1] = ev.y;
        sE[wl][lane][2] = ev.z; sE[wl][lane][3] = ev.w;
        __syncwarp();
        int cnt = min(32, deg - base);
        const float* sEj = &sE[wl][0][0];
#pragma unroll 8
        for (int j = 0; j < cnt; j++) {
            int sj = __shfl_sync(0xffffffffu, s, j);
            float e0 = sEj[j * 4 + h0];
            float e1 = sEj[j * 4 + 2 + h0];
            float2 f = __ldg((const float2*)(g_xp + (size_t)sj * HC + 2 * lane));
            acc0 = fmaf(f.x, e0, acc0);
            acc1 = fmaf(f.y, e1, acc1);
        }
        __syncwarp();
    }
#pragma unroll
    for (int o = 16; o >= 1; o >>= 1) {
        ds.x += __shfl_xor_sync(0xffffffffu, ds.x, o);
        ds.y += __shfl_xor_sync(0xffffffffu, ds.y, o);
        ds.z += __shfl_xor_sync(0xffffffffu, ds.z, o);
        ds.w += __shfl_xor_sync(0xffffffffu, ds.w, o);
    }
    float4 r;
    r.x = 1.f / (ds.x + 1e-16f); r.y = 1.f / (ds.y + 1e-16f);
    r.z = 1.f / (ds.z + 1e-16f); r.w = 1.f / (ds.w + 1e-16f);
    if (lane == 0) g_rcp4[w] = r;

    float r0 = h0 ? r.y : r.x;
    float r1 = h0 ? r.w : r.z;
    out[(size_t)w * HC + lane]      = acc0 * r0 + bias[lane];
    out[(size_t)w * HC + 32 + lane] = acc1 * r1 + bias[lane + 32];
}

// ---------------- alpha in edge order (coalesced) ----------------
__global__ __launch_bounds__(256) void alpha_kernel(
    const int* __restrict__ ei, int e, float* __restrict__ alpha_out)
{
    int t = blockIdx.x * blockDim.x + threadIdx.x;
    if (t >= e) return;
    int s = ei[t], d = ei[e + t];
    float4 a = g_as4[s];
    float4 b = g_ad4[d];
    float4 r = g_rcp4[d];
    float4 o;
    o.x = __expf(lrelu(a.x + b.x)) * r.x;
    o.y = __expf(lrelu(a.y + b.y)) * r.y;
    o.z = __expf(lrelu(a.z + b.z)) * r.z;
    o.w = __expf(lrelu(a.w + b.w)) * r.w;
    ((float4*)alpha_out)[t] = o;
}

extern "C" void kernel_launch(void* const* d_in, const int* in_sizes, int n_in,
                              void* d_out, int out_size) {
    const float* x       = (const float*)d_in[0];
    const float* W       = (const float*)d_in[1];
    const float* att_src = (const float*)d_in[2];
    const float* att_dst = (const float*)d_in[3];
    const float* bias    = (const float*)d_in[4];
    const int*   ei      = (const int*)d_in[5];
    float* out = (float*)d_out;

    int n = in_sizes[0] / IN_DIM;   // 100000
    int e = in_sizes[5] / 2;        // 1600000
    long nhc = (long)n * HC;
    int nb = (n + 511) / 512;

    float* ei_out = nullptr;
    float* alpha_out = nullptr;
    if ((long)out_size >= nhc + 2L * e)          ei_out    = out + nhc;
    if ((long)out_size >= nhc + 2L * e + 4L * e) alpha_out = out + nhc + 2L * e;

    cudaFuncSetAttribute(gemm_kernel,
                         cudaFuncAttributeMaxDynamicSharedMemorySize, GEMM_SMEM_BYTES);

    // order chosen so the profiler's captured launch (index 3) is the GEMM
    init_kernel<<<(n + 511) / 512, 512>>>(n);
    hist_kernel<<<((e + 3) / 4 + 255) / 256, 256>>>(ei, e, ei_out);
    scan1_kernel<<<nb, 512>>>(n);
    gemm_kernel<<<(n + 127) / 128, 256, GEMM_SMEM_BYTES>>>(x, W, att_src, att_dst, n);
    scan2_kernel<<<1, 512>>>(nb);
    scan3_kernel<<<nb, 512>>>(n);
    fill_kernel<<<(e + 255) / 256, 256>>>(ei, e);
    aggregate_kernel<<<(n * 32 + 255) / 256, 256>>>(bias, out, n);

    if (alpha_out)
        alpha_kernel<<<(e + 255) / 256, 256>>>(ei, e, alpha_out);
}

// round 10
// speedup vs baseline: 1.1065x; 1.1065x over previous
#include <cuda_runtime.h>
#include <math.h>

#define NN 100000
#define EE 1600000
#define HC 64
#define IN_DIM 128

// ---------------- scratch (device globals, allocation-free) ----------------
// g_xp holds xp in interleaved-pair layout: element 2c   = xp[node][c]
//                                           element 2c+1 = xp[node][c+32]  (c = 0..31)
static __device__ float  g_xp[(size_t)NN * HC];
static __device__ float4 g_as4[NN];               // a_src [N,4]
static __device__ float4 g_dpk[2 * NN];           // [2d]=a_dst, [2d+1]=rcp (adjacent gathers)
static __device__ int    g_cnt[NN];               // degree histogram
static __device__ int2   g_fc[NN];                // {row start, fill cursor}
static __device__ int    g_rowptr[NN + 1];        // CSR row pointers
static __device__ int    g_bsum[512];             // scan partials
static __device__ int    g_boff[512];             // scan offsets
static __device__ int    g_csr_src[EE];           // CSR src ids

__device__ __forceinline__ float lrelu(float v) { return v >= 0.f ? v : 0.2f * v; }

__device__ __forceinline__ float f2tf(float f) {
    unsigned u;
    asm("cvt.rna.tf32.f32 %0, %1;" : "=r"(u) : "f"(f));
    return __uint_as_float(u);
}
__device__ __forceinline__ void mma_tf32(float4& d,
    float a0, float a1, float a2, float a3, float b0, float b1)
{
    asm("mma.sync.aligned.m16n8k8.row.col.f32.tf32.tf32.f32 "
        "{%0,%1,%2,%3}, {%4,%5,%6,%7}, {%8,%9}, {%0,%1,%2,%3};"
        : "+f"(d.x), "+f"(d.y), "+f"(d.z), "+f"(d.w)
        : "r"(__float_as_uint(a0)), "r"(__float_as_uint(a1)),
          "r"(__float_as_uint(a2)), "r"(__float_as_uint(a3)),
          "r"(__float_as_uint(b0)), "r"(__float_as_uint(b1)));
}

// ---------------- init: zero histogram ----------------
__global__ void init_kernel(int n) {
    int i = blockIdx.x * blockDim.x + threadIdx.x;
    if (i < n) g_cnt[i] = 0;
}

// ---------------- GEMM: xp = x @ W via tf32 tensor cores + attn epilogue ----------------
// R8 byte-identical mainloop/epilogue (64x64 tile, static smem, 4 blocks/SM).
__global__ __launch_bounds__(256) void gemm_kernel(
    const float* __restrict__ x, const float* __restrict__ W,
    const float* __restrict__ att_src, const float* __restrict__ att_dst, int n)
{
    __shared__ float xs[64 * 68];   // [row][k-half], stride 68 (reused for C)
    __shared__ float ws[64 * 72];   // [k-half][col], stride 72
    int tid = threadIdx.x;
    int lane = tid & 31, warp = tid >> 5;
    int wm = warp & 3, wn = warp >> 2;
    int gid = lane >> 2, tig = lane & 3;
    int r0 = blockIdx.x * 64;

    float4 c[4];
#pragma unroll
    for (int t = 0; t < 4; t++) c[t] = make_float4(0.f, 0.f, 0.f, 0.f);

    for (int kh = 0; kh < 2; kh++) {
#pragma unroll
        for (int q = 0; q < 4; q++) {
            int idx = tid + q * 256;           // 0..1023
            int row = idx >> 4, k4 = idx & 15;
            float4 v = make_float4(0.f, 0.f, 0.f, 0.f);
            int grow = r0 + row;
            if (grow < n)
                v = *(const float4*)(x + (size_t)grow * IN_DIM + kh * 64 + k4 * 4);
            *(float4*)(xs + row * 68 + k4 * 4) =
                make_float4(f2tf(v.x), f2tf(v.y), f2tf(v.z), f2tf(v.w));
        }
#pragma unroll
        for (int q = 0; q < 4; q++) {
            int idx = tid + q * 256;
            int k = idx >> 4, c4 = idx & 15;
            float4 v = *(const float4*)(W + (size_t)(kh * 64 + k) * HC + c4 * 4);
            *(float4*)(ws + k * 72 + c4 * 4) =
                make_float4(f2tf(v.x), f2tf(v.y), f2tf(v.z), f2tf(v.w));
        }
        __syncthreads();
#pragma unroll
        for (int k8 = 0; k8 < 8; k8++) {
            int kb = k8 * 8;
            const float* xr = xs + (16 * wm + gid) * 68 + kb + tig;
            float a0 = xr[0];
            float a1 = xr[8 * 68];
            float a2 = xr[4];
            float a3 = xr[8 * 68 + 4];
            const float* wr = ws + (kb + tig) * 72 + 32 * wn + gid;
#pragma unroll
            for (int t = 0; t < 4; t++) {
                float b0 = wr[8 * t];
                float b1 = wr[4 * 72 + 8 * t];
                mma_tf32(c[t], a0, a1, a2, a3, b0, b1);
            }
        }
        __syncthreads();
    }

    // write C frags into xs [row][col 0..63]
    {
        int rlo = 16 * wm + gid;
        int cb  = 32 * wn + 2 * tig;
#pragma unroll
        for (int t = 0; t < 4; t++) {
            *(float2*)(xs + rlo * 68 + cb + 8 * t)       = make_float2(c[t].x, c[t].y);
            *(float2*)(xs + (rlo + 8) * 68 + cb + 8 * t) = make_float2(c[t].z, c[t].w);
        }
    }
    __syncthreads();

    // epilogue: thread = (row, quarter qd).
    {
        int row = tid >> 2, qd = tid & 3;
        int grow = r0 + row;
        if (grow < n) {
            float4 v[4], s4[4], d4[4];
#pragma unroll
            for (int i = 0; i < 4; i++) {
                v[i]  = *(const float4*)(xs + row * 68 + qd * 16 + 4 * i);
                s4[i] = __ldg((const float4*)(att_src + qd * 16 + 4 * i));
                d4[i] = __ldg((const float4*)(att_dst + qd * 16 + 4 * i));
            }
            float as = 0.f, ad = 0.f;
#pragma unroll
            for (int i = 0; i < 4; i++) {
                as += v[i].x * s4[i].x + v[i].y * s4[i].y + v[i].z * s4[i].z + v[i].w * s4[i].w;
                ad += v[i].x * d4[i].x + v[i].y * d4[i].y + v[i].z * d4[i].z + v[i].w * d4[i].w;
            }
            ((float*)&g_as4[grow])[qd] = as;
            ((float*)&g_dpk[2 * (size_t)grow])[qd] = ad;
#pragma unroll
            for (int i = 0; i < 2; i++) {
                float4 A4 = *(const float4*)(xs + row * 68 + 8 * qd + 4 * i);
                float4 B4 = *(const float4*)(xs + row * 68 + 8 * qd + 32 + 4 * i);
                float* dst = g_xp + (size_t)grow * HC + 2 * (8 * qd + 4 * i);
                *(float4*)(dst)     = make_float4(A4.x, B4.x, A4.y, B4.y);
                *(float4*)(dst + 4) = make_float4(A4.z, B4.z, A4.w, B4.w);
            }
        }
    }
}

// ---------------- CSR histogram + fused edge_index float copy ----------------
__global__ void hist_kernel(const int* __restrict__ ei, int e, float* __restrict__ ei_out) {
    int t = blockIdx.x * blockDim.x + threadIdx.x;
    int base = t * 4;
    if (base + 3 < e) {
        int4 d4 = *(const int4*)(ei + e + base);
        atomicAdd(&g_cnt[d4.x], 1);
        atomicAdd(&g_cnt[d4.y], 1);
        atomicAdd(&g_cnt[d4.z], 1);
        atomicAdd(&g_cnt[d4.w], 1);
        if (ei_out) {
            int4 s4 = *(const int4*)(ei + base);
            *(float4*)(ei_out + base) =
                make_float4((float)s4.x, (float)s4.y, (float)s4.z, (float)s4.w);
            *(float4*)(ei_out + e + base) =
                make_float4((float)d4.x, (float)d4.y, (float)d4.z, (float)d4.w);
        }
    } else {
        for (int i = base; i < e; i++) {
            int s = ei[i], d = ei[e + i];
            atomicAdd(&g_cnt[d], 1);
            if (ei_out) { ei_out[i] = (float)s; ei_out[e + i] = (float)d; }
        }
    }
}

__global__ void scan1_kernel(int n) {
    __shared__ int sd[512];
    int t = threadIdx.x, i = blockIdx.x * 512 + t;
    int v = (i < n) ? g_cnt[i] : 0;
    sd[t] = v; __syncthreads();
    for (int off = 1; off < 512; off <<= 1) {
        int x = (t >= off) ? sd[t - off] : 0;
        __syncthreads();
        sd[t] += x;
        __syncthreads();
    }
    if (i < n) g_rowptr[i + 1] = sd[t];
    if (t == 511) g_bsum[blockIdx.x] = sd[511];
}

__global__ void scan2_kernel(int nb) {
    __shared__ int sd[512];
    int t = threadIdx.x;
    int v = (t < nb) ? g_bsum[t] : 0;
    sd[t] = v; __syncthreads();
    for (int off = 1; off < 512; off <<= 1) {
        int x = (t >= off) ? sd[t - off] : 0;
        __syncthreads();
        sd[t] += x;
        __syncthreads();
    }
    g_boff[t] = sd[t] - v;   // exclusive
}

// adds block offsets AND initializes fill cursors {start, 0}
__global__ void scan3_kernel(int n) {
    int t = threadIdx.x;
    int i = blockIdx.x * 512 + t;
    int inc = g_boff[blockIdx.x];
    int prev = 0;
    if (i < n && t > 0) prev = g_rowptr[i];     // scan1 value at i (pre-offset)
    __syncthreads();
    if (i < n) {
        g_rowptr[i + 1] += inc;
        g_fc[i] = make_int2(prev + inc, 0);
        if (i == 0) g_rowptr[0] = 0;
    }
}

// 4 edges per thread: vectorized reads, 4 independent atomic chains
__global__ void fill_kernel(const int* __restrict__ ei, int e) {
    int t = blockIdx.x * blockDim.x + threadIdx.x;
    int base = t * 4;
    if (base + 3 < e) {
        int4 s4 = *(const int4*)(ei + base);
        int4 d4 = *(const int4*)(ei + e + base);
        int2* f0 = &g_fc[d4.x]; int p0 = atomicAdd(&f0->y, 1);
        int2* f1 = &g_fc[d4.y]; int p1 = atomicAdd(&f1->y, 1);
        int2* f2 = &g_fc[d4.z]; int p2 = atomicAdd(&f2->y, 1);
        int2* f3 = &g_fc[d4.w]; int p3 = atomicAdd(&f3->y, 1);
        g_csr_src[f0->x + p0] = s4.x;
        g_csr_src[f1->x + p1] = s4.y;
        g_csr_src[f2->x + p2] = s4.z;
        g_csr_src[f3->x + p3] = s4.w;
    } else {
        for (int i = base; i < e; i++) {
            int s = ei[i], d = ei[e + i];
            int2* fc = &g_fc[d];
            int pos = atomicAdd(&fc->y, 1);
            g_csr_src[fc->x + pos] = s;
        }
    }
}

// ---------------- fused softmax + aggregation: one warp per dst node ----------------
__global__ __launch_bounds__(256) void aggregate_kernel(
    const float* __restrict__ bias, float* __restrict__ out, int n)
{
    __shared__ float sE[8][32][4];
    int w = (blockIdx.x * 256 + threadIdx.x) >> 5;
    int lane = threadIdx.x & 31, wl = threadIdx.x >> 5;
    if (w >= n) return;                 // uniform per warp

    int start = g_rowptr[w];
    int deg   = g_rowptr[w + 1] - start;
    float4 ad = g_dpk[2 * (size_t)w];

    float4 ds = make_float4(0.f, 0.f, 0.f, 0.f);
    float acc0 = 0.f, acc1 = 0.f;
    int h0 = lane >> 4;      // head of col=lane; col=lane+32 is head h0+2

    for (int base = 0; base < deg; base += 32) {
        int i = base + lane;
        int s = 0;
        float4 ev = make_float4(0.f, 0.f, 0.f, 0.f);
        if (i < deg) {
            s = g_csr_src[start + i];
            float4 a = g_as4[s];
            ev.x = __expf(lrelu(a.x + ad.x));
            ev.y = __expf(lrelu(a.y + ad.y));
            ev.z = __expf(lrelu(a.z + ad.z));
            ev.w = __expf(lrelu(a.w + ad.w));
            ds.x += ev.x; ds.y += ev.y; ds.z += ev.z; ds.w += ev.w;
        }
        sE[wl][lane][0] = ev.x; sE[wl][lane][1] = ev.y;
        sE[wl][lane][2] = ev.z; sE[wl][lane][3] = ev.w;
        __syncwarp();
        int cnt = min(32, deg - base);
        const float* sEj = &sE[wl][0][0];
#pragma unroll 8
        for (int j = 0; j < cnt; j++) {
            int sj = __shfl_sync(0xffffffffu, s, j);
            float e0 = sEj[j * 4 + h0];
            float e1 = sEj[j * 4 + 2 + h0];
            float2 f = __ldg((const float2*)(g_xp + (size_t)sj * HC + 2 * lane));
            acc0 = fmaf(f.x, e0, acc0);
            acc1 = fmaf(f.y, e1, acc1);
        }
        __syncwarp();
    }
#pragma unroll
    for (int o = 16; o >= 1; o >>= 1) {
        ds.x += __shfl_xor_sync(0xffffffffu, ds.x, o);
        ds.y += __shfl_xor_sync(0xffffffffu, ds.y, o);
        ds.z += __shfl_xor_sync(0xffffffffu, ds.z, o);
        ds.w += __shfl_xor_sync(0xffffffffu, ds.w, o);
    }
    float4 r;
    r.x = 1.f / (ds.x + 1e-16f); r.y = 1.f / (ds.y + 1e-16f);
    r.z = 1.f / (ds.z + 1e-16f); r.w = 1.f / (ds.w + 1e-16f);
    if (lane == 0) g_dpk[2 * (size_t)w + 1] = r;

    float r0 = h0 ? r.y : r.x;
    float r1 = h0 ? r.w : r.z;
    out[(size_t)w * HC + lane]      = acc0 * r0 + bias[lane];
    out[(size_t)w * HC + 32 + lane] = acc1 * r1 + bias[lane + 32];
}

// ---------------- alpha in edge order (coalesced) ----------------
__global__ __launch_bounds__(256) void alpha_kernel(
    const int* __restrict__ ei, int e, float* __restrict__ alpha_out)
{
    int t = blockIdx.x * blockDim.x + threadIdx.x;
    if (t >= e) return;
    int s = ei[t], d = ei[e + t];
    float4 a = g_as4[s];
    float4 b = g_dpk[2 * (size_t)d];        // a_dst
    float4 r = g_dpk[2 * (size_t)d + 1];    // rcp (adjacent 16B — same sector)
    float4 o;
    o.x = __expf(lrelu(a.x + b.x)) * r.x;
    o.y = __expf(lrelu(a.y + b.y)) * r.y;
    o.z = __expf(lrelu(a.z + b.z)) * r.z;
    o.w = __expf(lrelu(a.w + b.w)) * r.w;
    ((float4*)alpha_out)[t] = o;
}

extern "C" void kernel_launch(void* const* d_in, const int* in_sizes, int n_in,
                              void* d_out, int out_size) {
    const float* x       = (const float*)d_in[0];
    const float* W       = (const float*)d_in[1];
    const float* att_src = (const float*)d_in[2];
    const float* att_dst = (const float*)d_in[3];
    const float* bias    = (const float*)d_in[4];
    const int*   ei      = (const int*)d_in[5];
    float* out = (float*)d_out;

    int n = in_sizes[0] / IN_DIM;   // 100000
    int e = in_sizes[5] / 2;        // 1600000
    long nhc = (long)n * HC;
    int nb = (n + 511) / 512;

    float* ei_out = nullptr;
    float* alpha_out = nullptr;
    if ((long)out_size >= nhc + 2L * e)          ei_out    = out + nhc;
    if ((long)out_size >= nhc + 2L * e + 4L * e) alpha_out = out + nhc + 2L * e;

    // order chosen so the profiler's captured launch (index 3) is the GEMM
    init_kernel<<<(n + 511) / 512, 512>>>(n);
    hist_kernel<<<((e + 3) / 4 + 255) / 256, 256>>>(ei, e, ei_out);
    scan1_kernel<<<nb, 512>>>(n);
    gemm_kernel<<<(n + 63) / 64, 256>>>(x, W, att_src, att_dst, n);
    scan2_kernel<<<1, 512>>>(nb);
    scan3_kernel<<<nb, 512>>>(n);
    fill_kernel<<<((e + 3) / 4 + 255) / 256, 256>>>(ei, e);
    aggregate_kernel<<<(n * 32 + 255) / 256, 256>>>(bias, out, n);

    if (alpha_out)
        alpha_kernel<<<(e + 255) / 256, 256>>>(ei, e, alpha_out);
}

// round 11
// speedup vs baseline: 1.1491x; 1.0384x over previous
#include <cuda_runtime.h>
#include <math.h>

#define NN 100000
#define EE 1600000
#define HC 64
#define IN_DIM 128

// ---------------- scratch (device globals, allocation-free) ----------------
// g_xp holds xp in interleaved-pair layout: element 2c   = xp[node][c]
//                                           element 2c+1 = xp[node][c+32]  (c = 0..31)
static __device__ float  g_xp[(size_t)NN * HC];
static __device__ float4 g_as4[NN];               // a_src [N,4]
static __device__ float4 g_dpk[2 * NN];           // [2d]=a_dst, [2d+1]=rcp (adjacent gathers)
static __device__ int    g_cnt[NN];               // degree histogram (zero-invariant between calls)
static __device__ int2   g_fc[NN];                // {row start, fill cursor}
static __device__ int    g_rowptr[NN + 1];        // CSR row pointers
static __device__ int    g_bsum[512];             // scan partials
static __device__ int    g_csr_src[EE];           // CSR src ids

__device__ __forceinline__ float lrelu(float v) { return v >= 0.f ? v : 0.2f * v; }

__device__ __forceinline__ float f2tf(float f) {
    unsigned u;
    asm("cvt.rna.tf32.f32 %0, %1;" : "=r"(u) : "f"(f));
    return __uint_as_float(u);
}
__device__ __forceinline__ void mma_tf32(float4& d,
    float a0, float a1, float a2, float a3, float b0, float b1)
{
    asm("mma.sync.aligned.m16n8k8.row.col.f32.tf32.tf32.f32 "
        "{%0,%1,%2,%3}, {%4,%5,%6,%7}, {%8,%9}, {%0,%1,%2,%3};"
        : "+f"(d.x), "+f"(d.y), "+f"(d.z), "+f"(d.w)
        : "r"(__float_as_uint(a0)), "r"(__float_as_uint(a1)),
          "r"(__float_as_uint(a2)), "r"(__float_as_uint(a3)),
          "r"(__float_as_uint(b0)), "r"(__float_as_uint(b1)));
}

// ---------------- fused GEMM + histogram (independent work, interleaved blocks) ----------
// Even blocks: R8-identical tf32 GEMM (64x64 tile) + attn epilogue.
// Odd blocks: degree histogram + edge_index float copy (4 edges/thread).
__global__ __launch_bounds__(256) void gemm_hist_kernel(
    const float* __restrict__ x, const float* __restrict__ W,
    const float* __restrict__ att_src, const float* __restrict__ att_dst, int n,
    const int* __restrict__ ei, int e, float* __restrict__ ei_out,
    int GB, int HB)
{
    __shared__ float xs[64 * 68];   // [row][k-half], stride 68 (reused for C)
    __shared__ float ws[64 * 72];   // [k-half][col], stride 72
    int bid = blockIdx.x;
    int minGH = GB < HB ? GB : HB;
    int gb = -1, hb = -1;
    if (bid < 2 * minGH) { if (bid & 1) hb = bid >> 1; else gb = bid >> 1; }
    else { int r = bid - 2 * minGH; if (GB > HB) gb = minGH + r; else hb = minGH + r; }

    if (hb >= 0) {
        // ---- histogram part ----
        int t = hb * blockDim.x + threadIdx.x;
        int base = t * 4;
        if (base + 3 < e) {
            int4 d4 = *(const int4*)(ei + e + base);
            atomicAdd(&g_cnt[d4.x], 1);
            atomicAdd(&g_cnt[d4.y], 1);
            atomicAdd(&g_cnt[d4.z], 1);
            atomicAdd(&g_cnt[d4.w], 1);
            if (ei_out) {
                int4 s4 = *(const int4*)(ei + base);
                *(float4*)(ei_out + base) =
                    make_float4((float)s4.x, (float)s4.y, (float)s4.z, (float)s4.w);
                *(float4*)(ei_out + e + base) =
                    make_float4((float)d4.x, (float)d4.y, (float)d4.z, (float)d4.w);
            }
        } else {
            for (int i = base; i < e; i++) {
                int s = ei[i], d = ei[e + i];
                atomicAdd(&g_cnt[d], 1);
                if (ei_out) { ei_out[i] = (float)s; ei_out[e + i] = (float)d; }
            }
        }
        return;
    }

    // ---- GEMM part (R8 byte-identical) ----
    int tid = threadIdx.x;
    int lane = tid & 31, warp = tid >> 5;
    int wm = warp & 3, wn = warp >> 2;
    int gid = lane >> 2, tig = lane & 3;
    int r0 = gb * 64;

    float4 c[4];
#pragma unroll
    for (int t = 0; t < 4; t++) c[t] = make_float4(0.f, 0.f, 0.f, 0.f);

    for (int kh = 0; kh < 2; kh++) {
#pragma unroll
        for (int q = 0; q < 4; q++) {
            int idx = tid + q * 256;           // 0..1023
            int row = idx >> 4, k4 = idx & 15;
            float4 v = make_float4(0.f, 0.f, 0.f, 0.f);
            int grow = r0 + row;
            if (grow < n)
                v = *(const float4*)(x + (size_t)grow * IN_DIM + kh * 64 + k4 * 4);
            *(float4*)(xs + row * 68 + k4 * 4) =
                make_float4(f2tf(v.x), f2tf(v.y), f2tf(v.z), f2tf(v.w));
        }
#pragma unroll
        for (int q = 0; q < 4; q++) {
            int idx = tid + q * 256;
            int k = idx >> 4, c4 = idx & 15;
            float4 v = *(const float4*)(W + (size_t)(kh * 64 + k) * HC + c4 * 4);
            *(float4*)(ws + k * 72 + c4 * 4) =
                make_float4(f2tf(v.x), f2tf(v.y), f2tf(v.z), f2tf(v.w));
        }
        __syncthreads();
#pragma unroll
        for (int k8 = 0; k8 < 8; k8++) {
            int kb = k8 * 8;
            const float* xr = xs + (16 * wm + gid) * 68 + kb + tig;
            float a0 = xr[0];
            float a1 = xr[8 * 68];
            float a2 = xr[4];
            float a3 = xr[8 * 68 + 4];
            const float* wr = ws + (kb + tig) * 72 + 32 * wn + gid;
#pragma unroll
            for (int t = 0; t < 4; t++) {
                float b0 = wr[8 * t];
                float b1 = wr[4 * 72 + 8 * t];
                mma_tf32(c[t], a0, a1, a2, a3, b0, b1);
            }
        }
        __syncthreads();
    }

    {
        int rlo = 16 * wm + gid;
        int cb  = 32 * wn + 2 * tig;
#pragma unroll
        for (int t = 0; t < 4; t++) {
            *(float2*)(xs + rlo * 68 + cb + 8 * t)       = make_float2(c[t].x, c[t].y);
            *(float2*)(xs + (rlo + 8) * 68 + cb + 8 * t) = make_float2(c[t].z, c[t].w);
        }
    }
    __syncthreads();

    {
        int row = tid >> 2, qd = tid & 3;
        int grow = r0 + row;
        if (grow < n) {
            float4 v[4], s4[4], d4[4];
#pragma unroll
            for (int i = 0; i < 4; i++) {
                v[i]  = *(const float4*)(xs + row * 68 + qd * 16 + 4 * i);
                s4[i] = __ldg((const float4*)(att_src + qd * 16 + 4 * i));
                d4[i] = __ldg((const float4*)(att_dst + qd * 16 + 4 * i));
            }
            float as = 0.f, ad = 0.f;
#pragma unroll
            for (int i = 0; i < 4; i++) {
                as += v[i].x * s4[i].x + v[i].y * s4[i].y + v[i].z * s4[i].z + v[i].w * s4[i].w;
                ad += v[i].x * d4[i].x + v[i].y * d4[i].y + v[i].z * d4[i].z + v[i].w * d4[i].w;
            }
            ((float*)&g_as4[grow])[qd] = as;
            ((float*)&g_dpk[2 * (size_t)grow])[qd] = ad;
#pragma unroll
            for (int i = 0; i < 2; i++) {
                float4 A4 = *(const float4*)(xs + row * 68 + 8 * qd + 4 * i);
                float4 B4 = *(const float4*)(xs + row * 68 + 8 * qd + 32 + 4 * i);
                float* dst = g_xp + (size_t)grow * HC + 2 * (8 * qd + 4 * i);
                *(float4*)(dst)     = make_float4(A4.x, B4.x, A4.y, B4.y);
                *(float4*)(dst + 4) = make_float4(A4.z, B4.z, A4.w, B4.w);
            }
        }
    }
}

// ---------------- scan1: per-block inclusive scan + restore g_cnt zeros ----------------
__global__ void scan1_kernel(int n) {
    __shared__ int sd[512];
    int t = threadIdx.x, i = blockIdx.x * 512 + t;
    int v = 0;
    if (i < n) { v = g_cnt[i]; g_cnt[i] = 0; }   // restore zero-invariant for next call
    sd[t] = v; __syncthreads();
    for (int off = 1; off < 512; off <<= 1) {
        int x = (t >= off) ? sd[t - off] : 0;
        __syncthreads();
        sd[t] += x;
        __syncthreads();
    }
    if (i < n) g_rowptr[i + 1] = sd[t];
    if (t == 511) g_bsum[blockIdx.x] = sd[511];
}

// ---------------- scan23: per-block spine reduce + apply offsets + init cursors ---------
__global__ void scan23_kernel(int n) {
    __shared__ int sd[512];
    int t = threadIdx.x;
    int v = (t < blockIdx.x) ? g_bsum[t] : 0;     // blockIdx.x <= 195 < 512
    sd[t] = v; __syncthreads();
#pragma unroll
    for (int off = 256; off >= 1; off >>= 1) {
        if (t < off) sd[t] += sd[t + off];
        __syncthreads();
    }
    int inc = sd[0];                              // exclusive spine prefix for this block
    int i = blockIdx.x * 512 + t;
    int prev = 0;
    if (i < n && t > 0) prev = g_rowptr[i];       // scan1 value at i (pre-offset)
    __syncthreads();
    if (i < n) {
        g_rowptr[i + 1] += inc;
        g_fc[i] = make_int2(prev + inc, 0);
        if (i == 0) g_rowptr[0] = 0;
    }
}

// 4 edges per thread: vectorized reads, 4 independent atomic chains
__global__ void fill_kernel(const int* __restrict__ ei, int e) {
    int t = blockIdx.x * blockDim.x + threadIdx.x;
    int base = t * 4;
    if (base + 3 < e) {
        int4 s4 = *(const int4*)(ei + base);
        int4 d4 = *(const int4*)(ei + e + base);
        int2* f0 = &g_fc[d4.x]; int p0 = atomicAdd(&f0->y, 1);
        int2* f1 = &g_fc[d4.y]; int p1 = atomicAdd(&f1->y, 1);
        int2* f2 = &g_fc[d4.z]; int p2 = atomicAdd(&f2->y, 1);
        int2* f3 = &g_fc[d4.w]; int p3 = atomicAdd(&f3->y, 1);
        g_csr_src[f0->x + p0] = s4.x;
        g_csr_src[f1->x + p1] = s4.y;
        g_csr_src[f2->x + p2] = s4.z;
        g_csr_src[f3->x + p3] = s4.w;
    } else {
        for (int i = base; i < e; i++) {
            int s = ei[i], d = ei[e + i];
            int2* fc = &g_fc[d];
            int pos = atomicAdd(&fc->y, 1);
            g_csr_src[fc->x + pos] = s;
        }
    }
}

// ---------------- fused softmax + aggregation: one warp per dst node ----------------
__global__ __launch_bounds__(256) void aggregate_kernel(
    const float* __restrict__ bias, float* __restrict__ out, int n)
{
    __shared__ float sE[8][32][4];
    int w = (blockIdx.x * 256 + threadIdx.x) >> 5;
    int lane = threadIdx.x & 31, wl = threadIdx.x >> 5;
    if (w >= n) return;                 // uniform per warp

    int start = g_rowptr[w];
    int deg   = g_rowptr[w + 1] - start;
    float4 ad = g_dpk[2 * (size_t)w];

    float4 ds = make_float4(0.f, 0.f, 0.f, 0.f);
    float acc0 = 0.f, acc1 = 0.f;
    int h0 = lane >> 4;      // head of col=lane; col=lane+32 is head h0+2

    for (int base = 0; base < deg; base += 32) {
        int i = base + lane;
        int s = 0;
        float4 ev = make_float4(0.f, 0.f, 0.f, 0.f);
        if (i < deg) {
            s = g_csr_src[start + i];
            float4 a = g_as4[s];
            ev.x = __expf(lrelu(a.x + ad.x));
            ev.y = __expf(lrelu(a.y + ad.y));
            ev.z = __expf(lrelu(a.z + ad.z));
            ev.w = __expf(lrelu(a.w + ad.w));
            ds.x += ev.x; ds.y += ev.y; ds.z += ev.z; ds.w += ev.w;
        }
        sE[wl][lane][0] = ev.x; sE[wl][lane][1] = ev.y;
        sE[wl][lane][2] = ev.z; sE[wl][lane][3] = ev.w;
        __syncwarp();
        int cnt = min(32, deg - base);
        const float* sEj = &sE[wl][0][0];
#pragma unroll 8
        for (int j = 0; j < cnt; j++) {
            int sj = __shfl_sync(0xffffffffu, s, j);
            float e0 = sEj[j * 4 + h0];
            float e1 = sEj[j * 4 + 2 + h0];
            float2 f = __ldg((const float2*)(g_xp + (size_t)sj * HC + 2 * lane));
            acc0 = fmaf(f.x, e0, acc0);
            acc1 = fmaf(f.y, e1, acc1);
        }
        __syncwarp();
    }
#pragma unroll
    for (int o = 16; o >= 1; o >>= 1) {
        ds.x += __shfl_xor_sync(0xffffffffu, ds.x, o);
        ds.y += __shfl_xor_sync(0xffffffffu, ds.y, o);
        ds.z += __shfl_xor_sync(0xffffffffu, ds.z, o);
        ds.w += __shfl_xor_sync(0xffffffffu, ds.w, o);
    }
    float4 r;
    r.x = 1.f / (ds.x + 1e-16f); r.y = 1.f / (ds.y + 1e-16f);
    r.z = 1.f / (ds.z + 1e-16f); r.w = 1.f / (ds.w + 1e-16f);
    if (lane == 0) g_dpk[2 * (size_t)w + 1] = r;

    float r0 = h0 ? r.y : r.x;
    float r1 = h0 ? r.w : r.z;
    out[(size_t)w * HC + lane]      = acc0 * r0 + bias[lane];
    out[(size_t)w * HC + 32 + lane] = acc1 * r1 + bias[lane + 32];
}

// ---------------- alpha in edge order (coalesced) ----------------
__global__ __launch_bounds__(256) void alpha_kernel(
    const int* __restrict__ ei, int e, float* __restrict__ alpha_out)
{
    int t = blockIdx.x * blockDim.x + threadIdx.x;
    if (t >= e) return;
    int s = ei[t], d = ei[e + t];
    float4 a = g_as4[s];
    float4 b = g_dpk[2 * (size_t)d];        // a_dst
    float4 r = g_dpk[2 * (size_t)d + 1];    // rcp (adjacent 16B — same sector)
    float4 o;
    o.x = __expf(lrelu(a.x + b.x)) * r.x;
    o.y = __expf(lrelu(a.y + b.y)) * r.y;
    o.z = __expf(lrelu(a.z + b.z)) * r.z;
    o.w = __expf(lrelu(a.w + b.w)) * r.w;
    ((float4*)alpha_out)[t] = o;
}

extern "C" void kernel_launch(void* const* d_in, const int* in_sizes, int n_in,
                              void* d_out, int out_size) {
    const float* x       = (const float*)d_in[0];
    const float* W       = (const float*)d_in[1];
    const float* att_src = (const float*)d_in[2];
    const float* att_dst = (const float*)d_in[3];
    const float* bias    = (const float*)d_in[4];
    const int*   ei      = (const int*)d_in[5];
    float* out = (float*)d_out;

    int n = in_sizes[0] / IN_DIM;   // 100000
    int e = in_sizes[5] / 2;        // 1600000
    long nhc = (long)n * HC;
    int nb = (n + 511) / 512;

    float* ei_out = nullptr;
    float* alpha_out = nullptr;
    if ((long)out_size >= nhc + 2L * e)          ei_out    = out + nhc;
    if ((long)out_size >= nhc + 2L * e + 4L * e) alpha_out = out + nhc + 2L * e;

    int GB = (n + 63) / 64;                     // gemm blocks
    int HB = ((e + 3) / 4 + 255) / 256;         // hist blocks

    gemm_hist_kernel<<<GB + HB, 256>>>(x, W, att_src, att_dst, n, ei, e, ei_out, GB, HB);
    scan1_kernel<<<nb, 512>>>(n);
    scan23_kernel<<<nb, 512>>>(n);
    fill_kernel<<<((e + 3) / 4 + 255) / 256, 256>>>(ei, e);
    aggregate_kernel<<<(n * 32 + 255) / 256, 256>>>(bias, out, n);

    if (alpha_out)
        alpha_kernel<<<(e + 255) / 256, 256>>>(ei, e, alpha_out);
}

// round 12
// speedup vs baseline: 1.1636x; 1.0126x over previous
#include <cuda_runtime.h>
#include <math.h>

#define NN 100000
#define EE 1600000
#define HC 64
#define IN_DIM 128

// ---------------- scratch (device globals, allocation-free) ----------------
// g_xp holds xp in interleaved-pair layout: element 2c   = xp[node][c]
//                                           element 2c+1 = xp[node][c+32]  (c = 0..31)
static __device__ float  g_xp[(size_t)NN * HC];
static __device__ float4 g_as4[NN];               // a_src [N,4]
static __device__ float4 g_dpk[2 * NN];           // [2d]=a_dst, [2d+1]=rcp (adjacent gathers)
static __device__ int    g_cnt[NN];               // degree histogram (zero-invariant between calls)
static __device__ int    g_fill[NN];              // absolute fill cursors (init to row start)
static __device__ int    g_rowptr[NN + 1];        // CSR row pointers
static __device__ int    g_bsum[512];             // scan partials
static __device__ int2   g_csr2[EE];              // CSR {src, edge_id}

__device__ __forceinline__ float lrelu(float v) { return v >= 0.f ? v : 0.2f * v; }

__device__ __forceinline__ float f2tf(float f) {
    unsigned u;
    asm("cvt.rna.tf32.f32 %0, %1;" : "=r"(u) : "f"(f));
    return __uint_as_float(u);
}
__device__ __forceinline__ void mma_tf32(float4& d,
    float a0, float a1, float a2, float a3, float b0, float b1)
{
    asm("mma.sync.aligned.m16n8k8.row.col.f32.tf32.tf32.f32 "
        "{%0,%1,%2,%3}, {%4,%5,%6,%7}, {%8,%9}, {%0,%1,%2,%3};"
        : "+f"(d.x), "+f"(d.y), "+f"(d.z), "+f"(d.w)
        : "r"(__float_as_uint(a0)), "r"(__float_as_uint(a1)),
          "r"(__float_as_uint(a2)), "r"(__float_as_uint(a3)),
          "r"(__float_as_uint(b0)), "r"(__float_as_uint(b1)));
}

// ---------------- fused GEMM + histogram (independent work, interleaved blocks) ----------
__global__ __launch_bounds__(256) void gemm_hist_kernel(
    const float* __restrict__ x, const float* __restrict__ W,
    const float* __restrict__ att_src, const float* __restrict__ att_dst, int n,
    const int* __restrict__ ei, int e, float* __restrict__ ei_out,
    int GB, int HB)
{
    __shared__ float xs[64 * 68];   // [row][k-half], stride 68 (reused for C)
    __shared__ float ws[64 * 72];   // [k-half][col], stride 72
    int bid = blockIdx.x;
    int minGH = GB < HB ? GB : HB;
    int gb = -1, hb = -1;
    if (bid < 2 * minGH) { if (bid & 1) hb = bid >> 1; else gb = bid >> 1; }
    else { int r = bid - 2 * minGH; if (GB > HB) gb = minGH + r; else hb = minGH + r; }

    if (hb >= 0) {
        // ---- histogram part ----
        int t = hb * blockDim.x + threadIdx.x;
        int base = t * 4;
        if (base + 3 < e) {
            int4 d4 = *(const int4*)(ei + e + base);
            atomicAdd(&g_cnt[d4.x], 1);
            atomicAdd(&g_cnt[d4.y], 1);
            atomicAdd(&g_cnt[d4.z], 1);
            atomicAdd(&g_cnt[d4.w], 1);
            if (ei_out) {
                int4 s4 = *(const int4*)(ei + base);
                *(float4*)(ei_out + base) =
                    make_float4((float)s4.x, (float)s4.y, (float)s4.z, (float)s4.w);
                *(float4*)(ei_out + e + base) =
                    make_float4((float)d4.x, (float)d4.y, (float)d4.z, (float)d4.w);
            }
        } else {
            for (int i = base; i < e; i++) {
                int s = ei[i], d = ei[e + i];
                atomicAdd(&g_cnt[d], 1);
                if (ei_out) { ei_out[i] = (float)s; ei_out[e + i] = (float)d; }
            }
        }
        return;
    }

    // ---- GEMM part (R8 byte-identical) ----
    int tid = threadIdx.x;
    int lane = tid & 31, warp = tid >> 5;
    int wm = warp & 3, wn = warp >> 2;
    int gid = lane >> 2, tig = lane & 3;
    int r0 = gb * 64;

    float4 c[4];
#pragma unroll
    for (int t = 0; t < 4; t++) c[t] = make_float4(0.f, 0.f, 0.f, 0.f);

    for (int kh = 0; kh < 2; kh++) {
#pragma unroll
        for (int q = 0; q < 4; q++) {
            int idx = tid + q * 256;           // 0..1023
            int row = idx >> 4, k4 = idx & 15;
            float4 v = make_float4(0.f, 0.f, 0.f, 0.f);
            int grow = r0 + row;
            if (grow < n)
                v = *(const float4*)(x + (size_t)grow * IN_DIM + kh * 64 + k4 * 4);
            *(float4*)(xs + row * 68 + k4 * 4) =
                make_float4(f2tf(v.x), f2tf(v.y), f2tf(v.z), f2tf(v.w));
        }
#pragma unroll
        for (int q = 0; q < 4; q++) {
            int idx = tid + q * 256;
            int k = idx >> 4, c4 = idx & 15;
            float4 v = *(const float4*)(W + (size_t)(kh * 64 + k) * HC + c4 * 4);
            *(float4*)(ws + k * 72 + c4 * 4) =
                make_float4(f2tf(v.x), f2tf(v.y), f2tf(v.z), f2tf(v.w));
        }
        __syncthreads();
#pragma unroll
        for (int k8 = 0; k8 < 8; k8++) {
            int kb = k8 * 8;
            const float* xr = xs + (16 * wm + gid) * 68 + kb + tig;
            float a0 = xr[0];
            float a1 = xr[8 * 68];
            float a2 = xr[4];
            float a3 = xr[8 * 68 + 4];
            const float* wr = ws + (kb + tig) * 72 + 32 * wn + gid;
#pragma unroll
            for (int t = 0; t < 4; t++) {
                float b0 = wr[8 * t];
                float b1 = wr[4 * 72 + 8 * t];
                mma_tf32(c[t], a0, a1, a2, a3, b0, b1);
            }
        }
        __syncthreads();
    }

    {
        int rlo = 16 * wm + gid;
        int cb  = 32 * wn + 2 * tig;
#pragma unroll
        for (int t = 0; t < 4; t++) {
            *(float2*)(xs + rlo * 68 + cb + 8 * t)       = make_float2(c[t].x, c[t].y);
            *(float2*)(xs + (rlo + 8) * 68 + cb + 8 * t) = make_float2(c[t].z, c[t].w);
        }
    }
    __syncthreads();

    {
        int row = tid >> 2, qd = tid & 3;
        int grow = r0 + row;
        if (grow < n) {
            float4 v[4], s4[4], d4[4];
#pragma unroll
            for (int i = 0; i < 4; i++) {
                v[i]  = *(const float4*)(xs + row * 68 + qd * 16 + 4 * i);
                s4[i] = __ldg((const float4*)(att_src + qd * 16 + 4 * i));
                d4[i] = __ldg((const float4*)(att_dst + qd * 16 + 4 * i));
            }
            float as = 0.f, ad = 0.f;
#pragma unroll
            for (int i = 0; i < 4; i++) {
                as += v[i].x * s4[i].x + v[i].y * s4[i].y + v[i].z * s4[i].z + v[i].w * s4[i].w;
                ad += v[i].x * d4[i].x + v[i].y * d4[i].y + v[i].z * d4[i].z + v[i].w * d4[i].w;
            }
            ((float*)&g_as4[grow])[qd] = as;
            ((float*)&g_dpk[2 * (size_t)grow])[qd] = ad;
#pragma unroll
            for (int i = 0; i < 2; i++) {
                float4 A4 = *(const float4*)(xs + row * 68 + 8 * qd + 4 * i);
                float4 B4 = *(const float4*)(xs + row * 68 + 8 * qd + 32 + 4 * i);
                float* dst = g_xp + (size_t)grow * HC + 2 * (8 * qd + 4 * i);
                *(float4*)(dst)     = make_float4(A4.x, B4.x, A4.y, B4.y);
                *(float4*)(dst + 4) = make_float4(A4.z, B4.z, A4.w, B4.w);
            }
        }
    }
}

// ---------------- scan1: per-block inclusive scan + restore g_cnt zeros ----------------
__global__ void scan1_kernel(int n) {
    __shared__ int sd[512];
    int t = threadIdx.x, i = blockIdx.x * 512 + t;
    int v = 0;
    if (i < n) { v = g_cnt[i]; g_cnt[i] = 0; }   // restore zero-invariant for next call
    sd[t] = v; __syncthreads();
    for (int off = 1; off < 512; off <<= 1) {
        int x = (t >= off) ? sd[t - off] : 0;
        __syncthreads();
        sd[t] += x;
        __syncthreads();
    }
    if (i < n) g_rowptr[i + 1] = sd[t];
    if (t == 511) g_bsum[blockIdx.x] = sd[511];
}

// ---------------- scan23: spine reduce + apply offsets + init absolute cursors ---------
__global__ void scan23_kernel(int n) {
    __shared__ int sd[512];
    int t = threadIdx.x;
    int v = (t < blockIdx.x) ? g_bsum[t] : 0;     // blockIdx.x <= 195 < 512
    sd[t] = v; __syncthreads();
#pragma unroll
    for (int off = 256; off >= 1; off >>= 1) {
        if (t < off) sd[t] += sd[t + off];
        __syncthreads();
    }
    int inc = sd[0];                              // exclusive spine prefix for this block
    int i = blockIdx.x * 512 + t;
    int prev = 0;
    if (i < n && t > 0) prev = g_rowptr[i];       // scan1 value at i (pre-offset)
    __syncthreads();
    if (i < n) {
        g_rowptr[i + 1] += inc;
        g_fill[i] = prev + inc;                   // absolute start
        if (i == 0) g_rowptr[0] = 0;
    }
}

// 8 edges/thread; atomic returns absolute CSR position (no dependent load)
__global__ void fill_kernel(const int* __restrict__ ei, int e) {
    int t = blockIdx.x * blockDim.x + threadIdx.x;
    int base = t * 8;
    if (base + 7 < e) {
        int4 sa = *(const int4*)(ei + base);
        int4 sb = *(const int4*)(ei + base + 4);
        int4 da = *(const int4*)(ei + e + base);
        int4 db = *(const int4*)(ei + e + base + 4);
        int p0 = atomicAdd(&g_fill[da.x], 1);
        int p1 = atomicAdd(&g_fill[da.y], 1);
        int p2 = atomicAdd(&g_fill[da.z], 1);
        int p3 = atomicAdd(&g_fill[da.w], 1);
        int p4 = atomicAdd(&g_fill[db.x], 1);
        int p5 = atomicAdd(&g_fill[db.y], 1);
        int p6 = atomicAdd(&g_fill[db.z], 1);
        int p7 = atomicAdd(&g_fill[db.w], 1);
        g_csr2[p0] = make_int2(sa.x, base + 0);
        g_csr2[p1] = make_int2(sa.y, base + 1);
        g_csr2[p2] = make_int2(sa.z, base + 2);
        g_csr2[p3] = make_int2(sa.w, base + 3);
        g_csr2[p4] = make_int2(sb.x, base + 4);
        g_csr2[p5] = make_int2(sb.y, base + 5);
        g_csr2[p6] = make_int2(sb.z, base + 6);
        g_csr2[p7] = make_int2(sb.w, base + 7);
    } else {
        for (int i = base; i < e; i++) {
            int s = ei[i], d = ei[e + i];
            int pos = atomicAdd(&g_fill[d], 1);
            g_csr2[pos] = make_int2(s, i);
        }
    }
}

// ---------------- fused softmax + aggregation + raw-alpha scatter ----------------
// One warp per dst node. Stage 1 also writes unnormalized ev to alpha_out[eid].
__global__ __launch_bounds__(256) void aggregate_kernel(
    const float* __restrict__ bias, float* __restrict__ out,
    float* __restrict__ alpha_out, int n)
{
    __shared__ float sE[8][32][4];
    int w = (blockIdx.x * 256 + threadIdx.x) >> 5;
    int lane = threadIdx.x & 31, wl = threadIdx.x >> 5;
    if (w >= n) return;                 // uniform per warp

    int start = g_rowptr[w];
    int deg   = g_rowptr[w + 1] - start;
    float4 ad = g_dpk[2 * (size_t)w];

    float4 ds = make_float4(0.f, 0.f, 0.f, 0.f);
    float acc0 = 0.f, acc1 = 0.f;
    int h0 = lane >> 4;      // head of col=lane; col=lane+32 is head h0+2

    for (int base = 0; base < deg; base += 32) {
        int i = base + lane;
        int s = 0;
        float4 ev = make_float4(0.f, 0.f, 0.f, 0.f);
        if (i < deg) {
            int2 se = g_csr2[start + i];
            s = se.x;
            float4 a = g_as4[s];
            ev.x = __expf(lrelu(a.x + ad.x));
            ev.y = __expf(lrelu(a.y + ad.y));
            ev.z = __expf(lrelu(a.z + ad.z));
            ev.w = __expf(lrelu(a.w + ad.w));
            ds.x += ev.x; ds.y += ev.y; ds.z += ev.z; ds.w += ev.w;
            if (alpha_out) ((float4*)alpha_out)[se.y] = ev;   // raw, scaled later
        }
        sE[wl][lane][0] = ev.x; sE[wl][lane][1] = ev.y;
        sE[wl][lane][2] = ev.z; sE[wl][lane][3] = ev.w;
        __syncwarp();
        int cnt = min(32, deg - base);
        const float* sEj = &sE[wl][0][0];
#pragma unroll 8
        for (int j = 0; j < cnt; j++) {
            int sj = __shfl_sync(0xffffffffu, s, j);
            float e0 = sEj[j * 4 + h0];
            float e1 = sEj[j * 4 + 2 + h0];
            float2 f = __ldg((const float2*)(g_xp + (size_t)sj * HC + 2 * lane));
            acc0 = fmaf(f.x, e0, acc0);
            acc1 = fmaf(f.y, e1, acc1);
        }
        __syncwarp();
    }
#pragma unroll
    for (int o = 16; o >= 1; o >>= 1) {
        ds.x += __shfl_xor_sync(0xffffffffu, ds.x, o);
        ds.y += __shfl_xor_sync(0xffffffffu, ds.y, o);
        ds.z += __shfl_xor_sync(0xffffffffu, ds.z, o);
        ds.w += __shfl_xor_sync(0xffffffffu, ds.w, o);
    }
    float4 r;
    r.x = 1.f / (ds.x + 1e-16f); r.y = 1.f / (ds.y + 1e-16f);
    r.z = 1.f / (ds.z + 1e-16f); r.w = 1.f / (ds.w + 1e-16f);
    if (lane == 0) g_dpk[2 * (size_t)w + 1] = r;

    float r0 = h0 ? r.y : r.x;
    float r1 = h0 ? r.w : r.z;
    out[(size_t)w * HC + lane]      = acc0 * r0 + bias[lane];
    out[(size_t)w * HC + 32 + lane] = acc1 * r1 + bias[lane + 32];
}

// ---------------- alpha scale: alpha[t] *= rcp[dst[t]] (coalesced + 1 gather) ----------
__global__ __launch_bounds__(256) void alpha_scale_kernel(
    const int* __restrict__ ei, int e, float* __restrict__ alpha_out)
{
    int t = blockIdx.x * blockDim.x + threadIdx.x;
    if (t >= e) return;
    int d = ei[e + t];
    float4 r = g_dpk[2 * (size_t)d + 1];
    float4 a = ((const float4*)alpha_out)[t];
    a.x *= r.x; a.y *= r.y; a.z *= r.z; a.w *= r.w;
    ((float4*)alpha_out)[t] = a;
}

extern "C" void kernel_launch(void* const* d_in, const int* in_sizes, int n_in,
                              void* d_out, int out_size) {
    const float* x       = (const float*)d_in[0];
    const float* W       = (const float*)d_in[1];
    const float* att_src = (const float*)d_in[2];
    const float* att_dst = (const float*)d_in[3];
    const float* bias    = (const float*)d_in[4];
    const int*   ei      = (const int*)d_in[5];
    float* out = (float*)d_out;

    int n = in_sizes[0] / IN_DIM;   // 100000
    int e = in_sizes[5] / 2;        // 1600000
    long nhc = (long)n * HC;
    int nb = (n + 511) / 512;

    float* ei_out = nullptr;
    float* alpha_out = nullptr;
    if ((long)out_size >= nhc + 2L * e)          ei_out    = out + nhc;
    if ((long)out_size >= nhc + 2L * e + 4L * e) alpha_out = out + nhc + 2L * e;

    int GB = (n + 63) / 64;                     // gemm blocks
    int HB = ((e + 3) / 4 + 255) / 256;         // hist blocks

    gemm_hist_kernel<<<GB + HB, 256>>>(x, W, att_src, att_dst, n, ei, e, ei_out, GB, HB);
    scan1_kernel<<<nb, 512>>>(n);
    scan23_kernel<<<nb, 512>>>(n);
    fill_kernel<<<((e + 7) / 8 + 255) / 256, 256>>>(ei, e);
    aggregate_kernel<<<(n * 32 + 255) / 256, 256>>>(bias, out, alpha_out, n);

    if (alpha_out)
        alpha_scale_kernel<<<(e + 255) / 256, 256>>>(ei, e, alpha_out);
}

// round 14
// speedup vs baseline: 1.2231x; 1.0511x over previous
#include <cuda_runtime.h>
#include <cuda_fp16.h>
#include <math.h>

#define NN 100000
#define EE 1600000
#define HC 64
#define IN_DIM 128

// ---------------- scratch (device globals, allocation-free) ----------------
// g_xph holds xp in fp16 interleaved-pair layout:
//   half2 slot c (c=0..31) of node v = (xp[v][c], xp[v][c+32])
static __device__ __half2 g_xph[(size_t)NN * 32];
static __device__ float4 g_as4[NN];               // a_src [N,4]
static __device__ float4 g_dpk[2 * NN];           // [2d]=a_dst, [2d+1]=rcp (adjacent gathers)
static __device__ int    g_cnt[NN];               // degree histogram (zero-invariant between calls)
static __device__ int    g_fill[NN];              // absolute fill cursors (init to row start)
static __device__ int    g_rowptr[NN + 1];        // CSR row pointers
static __device__ int    g_bsum[512];             // scan partials
static __device__ int2   g_csr2[EE];              // CSR {src, edge_id}

__device__ __forceinline__ float lrelu(float v) { return v >= 0.f ? v : 0.2f * v; }

__device__ __forceinline__ float f2tf(float f) {
    unsigned u;
    asm("cvt.rna.tf32.f32 %0, %1;" : "=r"(u) : "f"(f));
    return __uint_as_float(u);
}
__device__ __forceinline__ void mma_tf32(float4& d,
    float a0, float a1, float a2, float a3, float b0, float b1)
{
    asm("mma.sync.aligned.m16n8k8.row.col.f32.tf32.tf32.f32 "
        "{%0,%1,%2,%3}, {%4,%5,%6,%7}, {%8,%9}, {%0,%1,%2,%3};"
        : "+f"(d.x), "+f"(d.y), "+f"(d.z), "+f"(d.w)
        : "r"(__float_as_uint(a0)), "r"(__float_as_uint(a1)),
          "r"(__float_as_uint(a2)), "r"(__float_as_uint(a3)),
          "r"(__float_as_uint(b0)), "r"(__float_as_uint(b1)));
}

// ---------------- fused GEMM + histogram (independent work, interleaved blocks) ----------
__global__ __launch_bounds__(256) void gemm_hist_kernel(
    const float* __restrict__ x, const float* __restrict__ W,
    const float* __restrict__ att_src, const float* __restrict__ att_dst, int n,
    const int* __restrict__ ei, int e, float* __restrict__ ei_out,
    int GB, int HB)
{
    __shared__ float xs[64 * 68];   // [row][k-half], stride 68 (reused for C)
    __shared__ float ws[64 * 72];   // [k-half][col], stride 72
    int bid = blockIdx.x;
    int minGH = GB < HB ? GB : HB;
    int gb = -1, hb = -1;
    if (bid < 2 * minGH) { if (bid & 1) hb = bid >> 1; else gb = bid >> 1; }
    else { int r = bid - 2 * minGH; if (GB > HB) gb = minGH + r; else hb = minGH + r; }

    if (hb >= 0) {
        // ---- histogram part ----
        int t = hb * blockDim.x + threadIdx.x;
        int base = t * 4;
        if (base + 3 < e) {
            int4 d4 = *(const int4*)(ei + e + base);
            atomicAdd(&g_cnt[d4.x], 1);
            atomicAdd(&g_cnt[d4.y], 1);
            atomicAdd(&g_cnt[d4.z], 1);
            atomicAdd(&g_cnt[d4.w], 1);
            if (ei_out) {
                int4 s4 = *(const int4*)(ei + base);
                *(float4*)(ei_out + base) =
                    make_float4((float)s4.x, (float)s4.y, (float)s4.z, (float)s4.w);
                *(float4*)(ei_out + e + base) =
                    make_float4((float)d4.x, (float)d4.y, (float)d4.z, (float)d4.w);
            }
        } else {
            for (int i = base; i < e; i++) {
                int s = ei[i], d = ei[e + i];
                atomicAdd(&g_cnt[d], 1);
                if (ei_out) { ei_out[i] = (float)s; ei_out[e + i] = (float)d; }
            }
        }
        return;
    }

    // ---- GEMM part (R8 byte-identical mainloop) ----
    int tid = threadIdx.x;
    int lane = tid & 31, warp = tid >> 5;
    int wm = warp & 3, wn = warp >> 2;
    int gid = lane >> 2, tig = lane & 3;
    int r0 = gb * 64;

    float4 c[4];
#pragma unroll
    for (int t = 0; t < 4; t++) c[t] = make_float4(0.f, 0.f, 0.f, 0.f);

    for (int kh = 0; kh < 2; kh++) {
#pragma unroll
        for (int q = 0; q < 4; q++) {
            int idx = tid + q * 256;           // 0..1023
            int row = idx >> 4, k4 = idx & 15;
            float4 v = make_float4(0.f, 0.f, 0.f, 0.f);
            int grow = r0 + row;
            if (grow < n)
                v = *(const float4*)(x + (size_t)grow * IN_DIM + kh * 64 + k4 * 4);
            *(float4*)(xs + row * 68 + k4 * 4) =
                make_float4(f2tf(v.x), f2tf(v.y), f2tf(v.z), f2tf(v.w));
        }
#pragma unroll
        for (int q = 0; q < 4; q++) {
            int idx = tid + q * 256;
            int k = idx >> 4, c4 = idx & 15;
            float4 v = *(const float4*)(W + (size_t)(kh * 64 + k) * HC + c4 * 4);
            *(float4*)(ws + k * 72 + c4 * 4) =
                make_float4(f2tf(v.x), f2tf(v.y), f2tf(v.z), f2tf(v.w));
        }
        __syncthreads();
#pragma unroll
        for (int k8 = 0; k8 < 8; k8++) {
            int kb = k8 * 8;
            const float* xr = xs + (16 * wm + gid) * 68 + kb + tig;
            float a0 = xr[0];
            float a1 = xr[8 * 68];
            float a2 = xr[4];
            float a3 = xr[8 * 68 + 4];
            const float* wr = ws + (kb + tig) * 72 + 32 * wn + gid;
#pragma unroll
            for (int t = 0; t < 4; t++) {
                float b0 = wr[8 * t];
                float b1 = wr[4 * 72 + 8 * t];
                mma_tf32(c[t], a0, a1, a2, a3, b0, b1);
            }
        }
        __syncthreads();
    }

    {
        int rlo = 16 * wm + gid;
        int cb  = 32 * wn + 2 * tig;
#pragma unroll
        for (int t = 0; t < 4; t++) {
            *(float2*)(xs + rlo * 68 + cb + 8 * t)       = make_float2(c[t].x, c[t].y);
            *(float2*)(xs + (rlo + 8) * 68 + cb + 8 * t) = make_float2(c[t].z, c[t].w);
        }
    }
    __syncthreads();

    {
        int row = tid >> 2, qd = tid & 3;
        int grow = r0 + row;
        if (grow < n) {
            float4 v[4], s4[4], d4[4];
#pragma unroll
            for (int i = 0; i < 4; i++) {
                v[i]  = *(const float4*)(xs + row * 68 + qd * 16 + 4 * i);
                s4[i] = __ldg((const float4*)(att_src + qd * 16 + 4 * i));
                d4[i] = __ldg((const float4*)(att_dst + qd * 16 + 4 * i));
            }
            float as = 0.f, ad = 0.f;
#pragma unroll
            for (int i = 0; i < 4; i++) {
                as += v[i].x * s4[i].x + v[i].y * s4[i].y + v[i].z * s4[i].z + v[i].w * s4[i].w;
                ad += v[i].x * d4[i].x + v[i].y * d4[i].y + v[i].z * d4[i].z + v[i].w * d4[i].w;
            }
            ((float*)&g_as4[grow])[qd] = as;
            ((float*)&g_dpk[2 * (size_t)grow])[qd] = ad;
            // xp half2 interleaved pairs: slot c in [8qd, 8qd+8): (xp[c], xp[c+32])
#pragma unroll
            for (int i = 0; i < 2; i++) {
                float4 A4 = *(const float4*)(xs + row * 68 + 8 * qd + 4 * i);
                float4 B4 = *(const float4*)(xs + row * 68 + 8 * qd + 32 + 4 * i);
                __half2 hp[4];
                hp[0] = __floats2half2_rn(A4.x, B4.x);
                hp[1] = __floats2half2_rn(A4.y, B4.y);
                hp[2] = __floats2half2_rn(A4.z, B4.z);
                hp[3] = __floats2half2_rn(A4.w, B4.w);
                *(uint4*)(g_xph + (size_t)grow * 32 + 8 * qd + 4 * i) = *(const uint4*)hp;
            }
        }
    }
}

// ---------------- scan1: per-block inclusive scan + restore g_cnt zeros ----------------
__global__ void scan1_kernel(int n) {
    __shared__ int sd[512];
    int t = threadIdx.x, i = blockIdx.x * 512 + t;
    int v = 0;
    if (i < n) { v = g_cnt[i]; g_cnt[i] = 0; }   // restore zero-invariant for next call
    sd[t] = v; __syncthreads();
    for (int off = 1; off < 512; off <<= 1) {
        int x = (t >= off) ? sd[t - off] : 0;
        __syncthreads();
        sd[t] += x;
        __syncthreads();
    }
    if (i < n) g_rowptr[i + 1] = sd[t];
    if (t == 511) g_bsum[blockIdx.x] = sd[511];
}

// ---------------- scan23: spine reduce + apply offsets + init absolute cursors ---------
__global__ void scan23_kernel(int n) {
    __shared__ int sd[512];
    int t = threadIdx.x;
    int v = (t < blockIdx.x) ? g_bsum[t] : 0;     // blockIdx.x <= 195 < 512
    sd[t] = v; __syncthreads();
#pragma unroll
    for (int off = 256; off >= 1; off >>= 1) {
        if (t < off) sd[t] += sd[t + off];
        __syncthreads();
    }
    int inc = sd[0];                              // exclusive spine prefix for this block
    int i = blockIdx.x * 512 + t;
    int prev = 0;
    if (i < n && t > 0) prev = g_rowptr[i];       // scan1 value at i (pre-offset)
    __syncthreads();
    if (i < n) {
        g_rowptr[i + 1] += inc;
        g_fill[i] = prev + inc;                   // absolute start
        if (i == 0) g_rowptr[0] = 0;
    }
}

// 8 edges/thread; atomic returns absolute CSR position (no dependent load)
__global__ void fill_kernel(const int* __restrict__ ei, int e) {
    int t = blockIdx.x * blockDim.x + threadIdx.x;
    int base = t * 8;
    if (base + 7 < e) {
        int4 sa = *(const int4*)(ei + base);
        int4 sb = *(const int4*)(ei + base + 4);
        int4 da = *(const int4*)(ei + e + base);
        int4 db = *(const int4*)(ei + e + base + 4);
        int p0 = atomicAdd(&g_fill[da.x], 1);
        int p1 = atomicAdd(&g_fill[da.y], 1);
        int p2 = atomicAdd(&g_fill[da.z], 1);
        int p3 = atomicAdd(&g_fill[da.w], 1);
        int p4 = atomicAdd(&g_fill[db.x], 1);
        int p5 = atomicAdd(&g_fill[db.y], 1);
        int p6 = atomicAdd(&g_fill[db.z], 1);
        int p7 = atomicAdd(&g_fill[db.w], 1);
        g_csr2[p0] = make_int2(sa.x, base + 0);
        g_csr2[p1] = make_int2(sa.y, base + 1);
        g_csr2[p2] = make_int2(sa.z, base + 2);
        g_csr2[p3] = make_int2(sa.w, base + 3);
        g_csr2[p4] = make_int2(sb.x, base + 4);
        g_csr2[p5] = make_int2(sb.y, base + 5);
        g_csr2[p6] = make_int2(sb.z, base + 6);
        g_csr2[p7] = make_int2(sb.w, base + 7);
    } else {
        for (int i = base; i < e; i++) {
            int s = ei[i], d = ei[e + i];
            int pos = atomicAdd(&g_fill[d], 1);
            g_csr2[pos] = make_int2(s, i);
        }
    }
}

// ---------------- fused softmax + aggregation + raw-alpha scatter ----------------
__global__ __launch_bounds__(256) void aggregate_kernel(
    const float* __restrict__ bias, float* __restrict__ out,
    float* __restrict__ alpha_out, int n)
{
    __shared__ float sE[8][32][4];
    int w = (blockIdx.x * 256 + threadIdx.x) >> 5;
    int lane = threadIdx.x & 31, wl = threadIdx.x >> 5;
    if (w >= n) return;                 // uniform per warp

    int start = g_rowptr[w];
    int deg   = g_rowptr[w + 1] - start;
    float4 ad = g_dpk[2 * (size_t)w];

    float4 ds = make_float4(0.f, 0.f, 0.f, 0.f);
    float acc0 = 0.f, acc1 = 0.f;
    int h0 = lane >> 4;      // head of col=lane; col=lane+32 is head h0+2

    for (int base = 0; base < deg; base += 32) {
        int i = base + lane;
        int s = 0;
        float4 ev = make_float4(0.f, 0.f, 0.f, 0.f);
        if (i < deg) {
            int2 se = g_csr2[start + i];
            s = se.x;
            float4 a = g_as4[s];
            ev.x = __expf(lrelu(a.x + ad.x));
            ev.y = __expf(lrelu(a.y + ad.y));
            ev.z = __expf(lrelu(a.z + ad.z));
            ev.w = __expf(lrelu(a.w + ad.w));
            ds.x += ev.x; ds.y += ev.y; ds.z += ev.z; ds.w += ev.w;
            if (alpha_out) ((float4*)alpha_out)[se.y] = ev;   // raw, scaled later
        }
        sE[wl][lane][0] = ev.x; sE[wl][lane][1] = ev.y;
        sE[wl][lane][2] = ev.z; sE[wl][lane][3] = ev.w;
        __syncwarp();
        int cnt = min(32, deg - base);
        const float* sEj = &sE[wl][0][0];
#pragma unroll 8
        for (int j = 0; j < cnt; j++) {
            int sj = __shfl_sync(0xffffffffu, s, j);
            float e0 = sEj[j * 4 + h0];
            float e1 = sEj[j * 4 + 2 + h0];
            float2 f = __half22float2(__ldg(g_xph + (size_t)sj * 32 + lane));
            acc0 = fmaf(f.x, e0, acc0);
            acc1 = fmaf(f.y, e1, acc1);
        }
        __syncwarp();
    }
#pragma unroll
    for (int o = 16; o >= 1; o >>= 1) {
        ds.x += __shfl_xor_sync(0xffffffffu, ds.x, o);
        ds.y += __shfl_xor_sync(0xffffffffu, ds.y, o);
        ds.z += __shfl_xor_sync(0xffffffffu, ds.z, o);
        ds.w += __shfl_xor_sync(0xffffffffu, ds.w, o);
    }
    float4 r;
    r.x = 1.f / (ds.x + 1e-16f); r.y = 1.f / (ds.y + 1e-16f);
    r.z = 1.f / (ds.z + 1e-16f); r.w = 1.f / (ds.w + 1e-16f);
    if (lane == 0) g_dpk[2 * (size_t)w + 1] = r;

    float r0 = h0 ? r.y : r.x;
    float r1 = h0 ? r.w : r.z;
    out[(size_t)w * HC + lane]      = acc0 * r0 + bias[lane];
    out[(size_t)w * HC + 32 + lane] = acc1 * r1 + bias[lane + 32];
}

// ---------------- alpha scale: alpha[t] *= rcp[dst[t]] (coalesced + 1 gather) ----------
__global__ __launch_bounds__(256) void alpha_scale_kernel(
    const int* __restrict__ ei, int e, float* __restrict__ alpha_out)
{
    int t = blockIdx.x * blockDim.x + threadIdx.x;
    if (t >= e) return;
    int d = ei[e + t];
    float4 r = g_dpk[2 * (size_t)d + 1];
    float4 a = ((const float4*)alpha_out)[t];
    a.x *= r.x; a.y *= r.y; a.z *= r.z; a.w *= r.w;
    ((float4*)alpha_out)[t] = a;
}

extern "C" void kernel_launch(void* const* d_in, const int* in_sizes, int n_in,
                              void* d_out, int out_size) {
    const float* x       = (const float*)d_in[0];
    const float* W       = (const float*)d_in[1];
    const float* att_src = (const float*)d_in[2];
    const float* att_dst = (const float*)d_in[3];
    const float* bias    = (const float*)d_in[4];
    const int*   ei      = (const int*)d_in[5];
    float* out = (float*)d_out;

    int n = in_sizes[0] / IN_DIM;   // 100000
    int e = in_sizes[5] / 2;        // 1600000
    long nhc = (long)n * HC;
    int nb = (n + 511) / 512;

    float* ei_out = nullptr;
    float* alpha_out = nullptr;
    if ((long)out_size >= nhc + 2L * e)          ei_out    = out + nhc;
    if ((long)out_size >= nhc + 2L * e + 4L * e) alpha_out = out + nhc + 2L * e;

    int GB = (n + 63) / 64;                     // gemm blocks
    int HB = ((e + 3) / 4 + 255) / 256;         // hist blocks

    gemm_hist_kernel<<<GB + HB, 256>>>(x, W, att_src, att_dst, n, ei, e, ei_out, GB, HB);
    scan1_kernel<<<nb, 512>>>(n);
    scan23_kernel<<<nb, 512>>>(n);
    fill_kernel<<<((e + 7) / 8 + 255) / 256, 256>>>(ei, e);
    aggregate_kernel<<<(n * 32 + 255) / 256, 256>>>(bias, out, alpha_out, n);

    if (alpha_out)
        alpha_scale_kernel<<<(e + 255) / 256, 256>>>(ei, e, alpha_out);
}